// round 2
// baseline (speedup 1.0000x reference)
#include <cuda_runtime.h>
#include <math.h>

#define N_NODES 50000
#define IN_CH   256
#define HID     256
#define OUT_CH  128
#define MAX_E   1600000

// ---------------- scratch (static device globals; no allocation) ----------------
__device__ int   g_is64;                               // edge_index stored as int64?
__device__ int   g_src[MAX_E];
__device__ int   g_dst[MAX_E];
__device__ float g_dis[N_NODES];                       // deg -> rsqrt(deg)
__device__ float g_h1[(size_t)N_NODES * HID];          // x @ W1
__device__ float g_a1[(size_t)N_NODES * HID];          // aggregated layer-1 (pre-relu)
__device__ float g_h2[(size_t)N_NODES * OUT_CH];       // relu(a1) @ W2
__device__ float g_a2[(size_t)N_NODES * OUT_CH];       // aggregated layer-2 (z)

// ---------------- edge-index dtype detect + normalize to int32 ----------------
// int64 storage: little-endian pairs (lo, hi); values in [0, 50000) => hi == 0.
// int32 storage: odd words are uniform values in [0, 50000); all-zero is impossible.
__global__ void k_detect64(const unsigned int* __restrict__ w) {
    if (threadIdx.x == 0 || blockIdx.x == 0) {
        int is64 = 1;
        #pragma unroll 1
        for (int i = 0; i < 64; i++) {
            if (w[2 * i + 1] != 0u) { is64 = 0; break; }
        }
        g_is64 = is64;
    }
}

__global__ void k_normalize_idx(const unsigned int* __restrict__ w, int E) {
    int e = blockIdx.x * blockDim.x + threadIdx.x;
    if (e >= E) return;
    if (g_is64) {
        g_src[e] = (int)w[2 * e];               // first E int64 = src
        g_dst[e] = (int)w[2 * (size_t)E + 2 * e];
    } else {
        g_src[e] = (int)w[e];                   // first E int32 = src
        g_dst[e] = (int)w[(size_t)E + e];
    }
}

// ---------------- degree kernels ----------------
__global__ void k_deg_init(float* __restrict__ deg, int n) {
    int i = blockIdx.x * blockDim.x + threadIdx.x;
    if (i < n) deg[i] = 1.0f;                          // self-loop contributes 1
}

__global__ void k_deg_count(const int* __restrict__ dst, float* __restrict__ deg, int E) {
    int e = blockIdx.x * blockDim.x + threadIdx.x;
    if (e < E) atomicAdd(&deg[dst[e]], 1.0f);
}

__global__ void k_deg_rsqrt(float* __restrict__ deg, int n) {
    int i = blockIdx.x * blockDim.x + threadIdx.x;
    if (i < n) deg[i] = rsqrtf(deg[i]);                // deg >= 1 always
}

// ---------------- tiled fp32 GEMM: C[M,N] = act(A[M,K]) @ B[K,N] ----------------
// BM=64, BN=64, BK=32, 16x16 threads, 4x4 per thread. RELU_A applies relu to A loads.
template<bool RELU_A>
__global__ __launch_bounds__(256, 2)
void k_sgemm(const float* __restrict__ A, const float* __restrict__ B,
             float* __restrict__ C, int M, int N, int K) {
    __shared__ float As[64][33];   // row-major A tile, padded (scalar broadcast reads)
    __shared__ float Bs[32][64];   // row-major B tile (float4 reads, conflict-free)

    const int tx = threadIdx.x, ty = threadIdx.y;
    const int tid = ty * 16 + tx;
    const int row0 = blockIdx.y * 64;
    const int col0 = blockIdx.x * 64;

    float acc[4][4];
    #pragma unroll
    for (int m = 0; m < 4; m++)
        #pragma unroll
        for (int nn = 0; nn < 4; nn++) acc[m][nn] = 0.0f;

    for (int k0 = 0; k0 < K; k0 += 32) {
        // load A tile 64x32 (coalesced: consecutive tid -> consecutive k)
        #pragma unroll
        for (int i = 0; i < 8; i++) {
            int idx = i * 256 + tid;
            int rr = idx >> 5, cc = idx & 31;
            int gr = row0 + rr;
            float v = (gr < M) ? A[(size_t)gr * K + k0 + cc] : 0.0f;
            if (RELU_A) v = fmaxf(v, 0.0f);
            As[rr][cc] = v;
        }
        // load B tile 32x64 (coalesced)
        #pragma unroll
        for (int i = 0; i < 8; i++) {
            int idx = i * 256 + tid;
            int rr = idx >> 6, cc = idx & 63;
            Bs[rr][cc] = B[(size_t)(k0 + rr) * N + col0 + cc];
        }
        __syncthreads();

        #pragma unroll
        for (int kk = 0; kk < 32; kk++) {
            float ar[4];
            #pragma unroll
            for (int m = 0; m < 4; m++) ar[m] = As[ty * 4 + m][kk];
            float4 b4 = *reinterpret_cast<const float4*>(&Bs[kk][tx * 4]);
            #pragma unroll
            for (int m = 0; m < 4; m++) {
                acc[m][0] += ar[m] * b4.x;
                acc[m][1] += ar[m] * b4.y;
                acc[m][2] += ar[m] * b4.z;
                acc[m][3] += ar[m] * b4.w;
            }
        }
        __syncthreads();
    }

    #pragma unroll
    for (int m = 0; m < 4; m++) {
        int gr = row0 + ty * 4 + m;
        if (gr < M) {
            float4 v = make_float4(acc[m][0], acc[m][1], acc[m][2], acc[m][3]);
            *reinterpret_cast<float4*>(&C[(size_t)gr * N + col0 + tx * 4]) = v;
        }
    }
}

// ---------------- self-loop + bias init: agg[i] = h[i] * dis[i]^2 + bias ----------------
template<int F>
__global__ void k_self_init(const float* __restrict__ h, const float* __restrict__ dis,
                            const float* __restrict__ bias, float* __restrict__ agg, int n) {
    int i = blockIdx.x * blockDim.x + threadIdx.x;     // over n * F/4 float4s
    int total = n * (F / 4);
    if (i >= total) return;
    int node = i / (F / 4);
    int c4 = i % (F / 4);
    float s = dis[node];
    s = s * s;
    float4 b4 = reinterpret_cast<const float4*>(bias)[c4];
    float4 v = reinterpret_cast<const float4*>(h)[i];
    v.x = fmaf(v.x, s, b4.x);
    v.y = fmaf(v.y, s, b4.y);
    v.z = fmaf(v.z, s, b4.z);
    v.w = fmaf(v.w, s, b4.w);
    reinterpret_cast<float4*>(agg)[i] = v;
}

// ---------------- edge scatter: agg[dst] += h[src] * dis[src]*dis[dst] ----------------
// One warp per edge; float4 gather + red.global.add.v4.f32 scatter.
template<int F>
__global__ __launch_bounds__(256)
void k_scatter(const float* __restrict__ h, const int* __restrict__ src,
               const int* __restrict__ dst, const float* __restrict__ dis,
               float* __restrict__ agg, int E) {
    int warp_id = (blockIdx.x * blockDim.x + threadIdx.x) >> 5;
    int lane = threadIdx.x & 31;
    if (warp_id >= E) return;
    int s = __ldg(&src[warp_id]);
    int d = __ldg(&dst[warp_id]);
    float norm = __ldg(&dis[s]) * __ldg(&dis[d]);
    const float4* hrow = reinterpret_cast<const float4*>(h + (size_t)s * F);
    float4* arow = reinterpret_cast<float4*>(agg + (size_t)d * F);
    #pragma unroll
    for (int c = lane; c < F / 4; c += 32) {
        float4 v = __ldg(&hrow[c]);
        v.x *= norm; v.y *= norm; v.z *= norm; v.w *= norm;
        asm volatile("red.global.add.v4.f32 [%0], {%1, %2, %3, %4};"
                     :: "l"(&arow[c]), "f"(v.x), "f"(v.y), "f"(v.z), "f"(v.w)
                     : "memory");
    }
}

// ---------------- decode: out[e] = dot(z[src[e]], z[dst[e]]) over 128 ----------------
__global__ __launch_bounds__(256)
void k_decode(const float* __restrict__ z, const int* __restrict__ src,
              const int* __restrict__ dst, float* __restrict__ out, int E) {
    int warp_id = (blockIdx.x * blockDim.x + threadIdx.x) >> 5;
    int lane = threadIdx.x & 31;
    if (warp_id >= E) return;
    int s = __ldg(&src[warp_id]);
    int d = __ldg(&dst[warp_id]);
    const float4* zs = reinterpret_cast<const float4*>(z + (size_t)s * OUT_CH);
    const float4* zd = reinterpret_cast<const float4*>(z + (size_t)d * OUT_CH);
    float4 a = __ldg(&zs[lane]);
    float4 b = __ldg(&zd[lane]);
    float dot = a.x * b.x + a.y * b.y + a.z * b.z + a.w * b.w;
    #pragma unroll
    for (int o = 16; o > 0; o >>= 1) dot += __shfl_xor_sync(0xFFFFFFFFu, dot, o);
    if (lane == 0) out[warp_id] = dot;
}

// ---------------- launch ----------------
extern "C" void kernel_launch(void* const* d_in, const int* in_sizes, int n_in,
                              void* d_out, int out_size) {
    const float* x  = (const float*)d_in[0];
    const unsigned int* eiw = (const unsigned int*)d_in[1];   // int32 OR int64 words
    const float* W1 = (const float*)d_in[2];
    const float* b1 = (const float*)d_in[3];
    const float* W2 = (const float*)d_in[4];
    const float* b2 = (const float*)d_in[5];
    float* out = (float*)d_out;

    const int n = in_sizes[0] / IN_CH;         // 50000
    const int E = in_sizes[1] / 2;             // 1600000

    int *src, *dst;
    float *dis, *h1, *a1, *h2, *a2;
    cudaGetSymbolAddress((void**)&src, g_src);
    cudaGetSymbolAddress((void**)&dst, g_dst);
    cudaGetSymbolAddress((void**)&dis, g_dis);
    cudaGetSymbolAddress((void**)&h1,  g_h1);
    cudaGetSymbolAddress((void**)&a1,  g_a1);
    cudaGetSymbolAddress((void**)&h2,  g_h2);
    cudaGetSymbolAddress((void**)&a2,  g_a2);

    // edge_index dtype detect + normalize to int32
    k_detect64<<<1, 32>>>(eiw);
    k_normalize_idx<<<(E + 255) / 256, 256>>>(eiw, E);

    // degrees -> deg_inv_sqrt
    k_deg_init <<<(n + 255) / 256, 256>>>(dis, n);
    k_deg_count<<<(E + 255) / 256, 256>>>(dst, dis, E);
    k_deg_rsqrt<<<(n + 255) / 256, 256>>>(dis, n);

    dim3 blk(16, 16);

    // layer 1: h1 = x @ W1 ; a1 = selfinit(h1)+b1 ; a1 += scatter(h1)
    {
        dim3 grd(HID / 64, (n + 63) / 64);
        k_sgemm<false><<<grd, blk>>>(x, W1, h1, n, HID, IN_CH);
        int t1 = n * (HID / 4);
        k_self_init<HID><<<(t1 + 255) / 256, 256>>>(h1, dis, b1, a1, n);
        k_scatter<HID><<<(E + 7) / 8, 256>>>(h1, src, dst, dis, a1, E);
    }

    // layer 2: h2 = relu(a1) @ W2 ; a2 = selfinit(h2)+b2 ; a2 += scatter(h2)
    {
        dim3 grd(OUT_CH / 64, (n + 63) / 64);
        k_sgemm<true><<<grd, blk>>>(a1, W2, h2, n, OUT_CH, HID);
        int t2 = n * (OUT_CH / 4);
        k_self_init<OUT_CH><<<(t2 + 255) / 256, 256>>>(h2, dis, b2, a2, n);
        k_scatter<OUT_CH><<<(E + 7) / 8, 256>>>(h2, src, dst, dis, a2, E);
    }

    // decode original edges
    k_decode<<<(E + 7) / 8, 256>>>(a2, src, dst, out, E);
}

// round 11
// speedup vs baseline: 1.3698x; 1.3698x over previous
#include <cuda_runtime.h>
#include <math.h>

#define N_NODES 50000
#define IN_CH   256
#define HID     256
#define OUT_CH  128
#define MAX_E   1600000

// ---------------- scratch (static device globals; no allocation) ----------------
__device__ int   g_is64;                                // edge_index stored as int64?
__device__ int   g_src[MAX_E];
__device__ int   g_dst[MAX_E];
__device__ int   g_cnt[N_NODES];                        // in-degree (no self-loop)
__device__ int   g_cursor[N_NODES];                     // CSR fill cursors
__device__ int   g_rowstart[N_NODES + 1];               // CSR row offsets
__device__ int   g_csr_src[MAX_E];                      // CSR: src ids grouped by dst
__device__ float g_dis[N_NODES];                        // rsqrt(deg) incl self-loop
__device__ float g_h1[(size_t)N_NODES * HID];           // x @ W1
__device__ float g_a1[(size_t)N_NODES * HID];           // aggregated layer-1 (pre-relu)
__device__ float g_h2[(size_t)N_NODES * OUT_CH];        // relu(a1) @ W2
__device__ float g_a2[(size_t)N_NODES * OUT_CH];        // aggregated layer-2 (z)

// ---------------- packed f32x2 FMA (Blackwell; ptxas never auto-fuses) ----------------
#define PACK_F32X2(out, lo, hi) \
    asm("mov.b64 %0, {%1, %2};" : "=l"(out) : "f"(lo), "f"(hi))
#define UNPACK_F32X2(lo, hi, in) \
    asm("mov.b64 {%0, %1}, %2;" : "=f"(lo), "=f"(hi) : "l"(in))
#define FMA_F32X2(acc, a, b) \
    asm("fma.rn.f32x2 %0, %1, %2, %0;" : "+l"(acc) : "l"(a), "l"(b))

// ---------------- zero init (graph-safe; avoids cudaMemsetAsync) ----------------
__global__ void k_zero2(int* __restrict__ a, int* __restrict__ b, int n) {
    int i = blockIdx.x * blockDim.x + threadIdx.x;
    if (i < n) { a[i] = 0; b[i] = 0; }
}

// ---------------- edge-index dtype detect ----------------
// int64 storage: little-endian (lo, hi) pairs; values < 50000 => hi word == 0.
// int32 storage: odd words are uniform in [0, 50000); 64 consecutive zeros impossible.
__global__ void k_detect64(const unsigned int* __restrict__ w) {
    if (blockIdx.x == 0 && threadIdx.x == 0) {
        int is64 = 1;
        #pragma unroll 1
        for (int i = 0; i < 64; i++)
            if (w[2 * i + 1] != 0u) { is64 = 0; break; }
        g_is64 = is64;
    }
}

// normalize to int32 src/dst + fused degree histogram
__global__ void k_normalize_hist(const unsigned int* __restrict__ w, int E) {
    int e = blockIdx.x * blockDim.x + threadIdx.x;
    if (e >= E) return;
    int s, d;
    if (g_is64) {
        s = (int)w[2 * (size_t)e];
        d = (int)w[2 * (size_t)E + 2 * (size_t)e];
    } else {
        s = (int)w[e];
        d = (int)w[(size_t)E + e];
    }
    g_src[e] = s;
    g_dst[e] = d;
    atomicAdd(&g_cnt[d], 1);
}

// ---------------- exclusive scan (CSR row offsets) + deg_inv_sqrt ----------------
__global__ void k_scan_dis(const int* __restrict__ cnt, int* __restrict__ rs,
                           float* __restrict__ dis, int n) {
    __shared__ int carry;
    __shared__ int tmp[1024];
    int t = threadIdx.x;
    if (t == 0) carry = 0;
    __syncthreads();
    for (int base = 0; base < n; base += 1024) {
        int i = base + t;
        int v = (i < n) ? cnt[i] : 0;
        if (i < n) dis[i] = rsqrtf((float)(v + 1));     // +1 self-loop
        tmp[t] = v;
        __syncthreads();
        #pragma unroll
        for (int off = 1; off < 1024; off <<= 1) {
            int add = (t >= off) ? tmp[t - off] : 0;
            __syncthreads();
            tmp[t] += add;
            __syncthreads();
        }
        int incl = tmp[t];
        int total = tmp[1023];
        if (i < n) rs[i] = carry + incl - v;            // exclusive
        __syncthreads();
        if (t == 0) carry += total;
        __syncthreads();
    }
    if (t == 0) rs[n] = carry;
}

__global__ void k_fill(const int* __restrict__ src, const int* __restrict__ dst,
                       const int* __restrict__ rs, int* __restrict__ cursor,
                       int* __restrict__ csr_src, int E) {
    int e = blockIdx.x * blockDim.x + threadIdx.x;
    if (e >= E) return;
    int d = dst[e];
    int pos = rs[d] + atomicAdd(&cursor[d], 1);
    csr_src[pos] = src[e];
}

// ---------------- GEMM: C[M,N] = act(A[M,K]) @ B[K,N] ----------------
// BM=128, BN=128, BK=16, 256 threads, 8x8 per thread, packed f32x2 FMA.
// Thread (tx,ty): rows row0+ty*8..+7, cols col0+tx*4..+3 and col0+64+tx*4..+3.
template<bool RELU_A>
__global__ __launch_bounds__(256, 2)
void k_sgemm(const float* __restrict__ A, const float* __restrict__ B,
             float* __restrict__ C, int M, int N, int K) {
    __shared__ float As[128][17];   // [m][k], padded
    __shared__ float Bs[16][128];   // [k][n]

    const int tid = threadIdx.x;
    const int tx = tid & 15, ty = tid >> 4;
    const int row0 = blockIdx.y * 128;
    const int col0 = blockIdx.x * 128;

    unsigned long long acc2[8][4];
    #pragma unroll
    for (int i = 0; i < 8; i++)
        #pragma unroll
        for (int p = 0; p < 4; p++) acc2[i][p] = 0ull;

    for (int k0 = 0; k0 < K; k0 += 16) {
        // A tile 128x16 = 512 float4, 2 per thread
        #pragma unroll
        for (int l = 0; l < 2; l++) {
            int idx = l * 256 + tid;
            int r = idx >> 2, c4 = idx & 3;
            int gr = row0 + r;
            float4 v = make_float4(0.f, 0.f, 0.f, 0.f);
            if (gr < M) v = *reinterpret_cast<const float4*>(&A[(size_t)gr * K + k0 + c4 * 4]);
            if (RELU_A) {
                v.x = fmaxf(v.x, 0.f); v.y = fmaxf(v.y, 0.f);
                v.z = fmaxf(v.z, 0.f); v.w = fmaxf(v.w, 0.f);
            }
            As[r][c4 * 4 + 0] = v.x; As[r][c4 * 4 + 1] = v.y;
            As[r][c4 * 4 + 2] = v.z; As[r][c4 * 4 + 3] = v.w;
        }
        // B tile 16x128 = 512 float4, 2 per thread, coalesced
        #pragma unroll
        for (int l = 0; l < 2; l++) {
            int idx = l * 256 + tid;
            int r = idx >> 5, c4 = idx & 31;
            float4 v = *reinterpret_cast<const float4*>(&B[(size_t)(k0 + r) * N + col0 + c4 * 4]);
            *reinterpret_cast<float4*>(&Bs[r][c4 * 4]) = v;
        }
        __syncthreads();

        #pragma unroll
        for (int kk = 0; kk < 16; kk++) {
            // B: two conflict-free float4 reads (cols tx*4 and 64+tx*4)
            float4 b0 = *reinterpret_cast<const float4*>(&Bs[kk][tx * 4]);
            float4 b1 = *reinterpret_cast<const float4*>(&Bs[kk][64 + tx * 4]);
            unsigned long long bp[4];
            PACK_F32X2(bp[0], b0.x, b0.y);
            PACK_F32X2(bp[1], b0.z, b0.w);
            PACK_F32X2(bp[2], b1.x, b1.y);
            PACK_F32X2(bp[3], b1.z, b1.w);
            #pragma unroll
            for (int i = 0; i < 8; i++) {
                float av = As[ty * 8 + i][kk];
                unsigned long long ap;
                PACK_F32X2(ap, av, av);
                FMA_F32X2(acc2[i][0], ap, bp[0]);
                FMA_F32X2(acc2[i][1], ap, bp[1]);
                FMA_F32X2(acc2[i][2], ap, bp[2]);
                FMA_F32X2(acc2[i][3], ap, bp[3]);
            }
        }
        __syncthreads();
    }

    #pragma unroll
    for (int i = 0; i < 8; i++) {
        int gr = row0 + ty * 8 + i;
        if (gr >= M) break;
        float4 v0, v1;
        UNPACK_F32X2(v0.x, v0.y, acc2[i][0]);
        UNPACK_F32X2(v0.z, v0.w, acc2[i][1]);
        UNPACK_F32X2(v1.x, v1.y, acc2[i][2]);
        UNPACK_F32X2(v1.z, v1.w, acc2[i][3]);
        *reinterpret_cast<float4*>(&C[(size_t)gr * N + col0 + tx * 4])      = v0;
        *reinterpret_cast<float4*>(&C[(size_t)gr * N + col0 + 64 + tx * 4]) = v1;
    }
}

// ---------------- CSR aggregation: out[d] = sum_{s in N(d)} h[s]*dis[s]*dis[d]
//                                           + h[d]*dis[d]^2 + bias ----------------
// One warp per dst node; register accumulation, 2-wide neighbor unroll for MLP.
template<int F>
__global__ __launch_bounds__(256)
void k_agg(const float* __restrict__ h, const int* __restrict__ rs,
           const int* __restrict__ csr_src, const float* __restrict__ dis,
           const float* __restrict__ bias, float* __restrict__ out, int n) {
    constexpr int V = F / 128;                          // float4s per lane (2 or 1)
    int d = (blockIdx.x * blockDim.x + threadIdx.x) >> 5;
    int lane = threadIdx.x & 31;
    if (d >= n) return;

    float dd = __ldg(&dis[d]);
    float s2 = dd * dd;
    const float4* hd = reinterpret_cast<const float4*>(h + (size_t)d * F);
    const float4* bb = reinterpret_cast<const float4*>(bias);

    float4 acc[V];
    #pragma unroll
    for (int v = 0; v < V; v++) {
        float4 hv = __ldg(&hd[lane + 32 * v]);
        float4 b4 = __ldg(&bb[lane + 32 * v]);
        acc[v].x = fmaf(hv.x, s2, b4.x);
        acc[v].y = fmaf(hv.y, s2, b4.y);
        acc[v].z = fmaf(hv.z, s2, b4.z);
        acc[v].w = fmaf(hv.w, s2, b4.w);
    }

    int i0 = __ldg(&rs[d]), i1 = __ldg(&rs[d + 1]);
    for (int base = i0; base < i1; base += 32) {
        int idx = base + lane;
        int sv = 0; float sd = 0.f;
        if (idx < i1) {
            sv = __ldg(&csr_src[idx]);
            sd = __ldg(&dis[sv]);
        }
        int cnt = min(32, i1 - base);
        int j = 0;
        // 2-wide unroll: 2*V independent LDG.128 in flight per step
        for (; j + 2 <= cnt; j += 2) {
            int sA     = __shfl_sync(0xFFFFFFFFu, sv, j);
            float nA   = __shfl_sync(0xFFFFFFFFu, sd, j) * dd;
            int sB     = __shfl_sync(0xFFFFFFFFu, sv, j + 1);
            float nB   = __shfl_sync(0xFFFFFFFFu, sd, j + 1) * dd;
            const float4* hA = reinterpret_cast<const float4*>(h + (size_t)sA * F);
            const float4* hB = reinterpret_cast<const float4*>(h + (size_t)sB * F);
            float4 va[V], vb[V];
            #pragma unroll
            for (int v = 0; v < V; v++) va[v] = __ldg(&hA[lane + 32 * v]);
            #pragma unroll
            for (int v = 0; v < V; v++) vb[v] = __ldg(&hB[lane + 32 * v]);
            #pragma unroll
            for (int v = 0; v < V; v++) {
                acc[v].x = fmaf(va[v].x, nA, acc[v].x);
                acc[v].y = fmaf(va[v].y, nA, acc[v].y);
                acc[v].z = fmaf(va[v].z, nA, acc[v].z);
                acc[v].w = fmaf(va[v].w, nA, acc[v].w);
                acc[v].x = fmaf(vb[v].x, nB, acc[v].x);
                acc[v].y = fmaf(vb[v].y, nB, acc[v].y);
                acc[v].z = fmaf(vb[v].z, nB, acc[v].z);
                acc[v].w = fmaf(vb[v].w, nB, acc[v].w);
            }
        }
        for (; j < cnt; j++) {
            int s     = __shfl_sync(0xFFFFFFFFu, sv, j);
            float nrm = __shfl_sync(0xFFFFFFFFu, sd, j) * dd;
            const float4* hs = reinterpret_cast<const float4*>(h + (size_t)s * F);
            #pragma unroll
            for (int v = 0; v < V; v++) {
                float4 hv = __ldg(&hs[lane + 32 * v]);
                acc[v].x = fmaf(hv.x, nrm, acc[v].x);
                acc[v].y = fmaf(hv.y, nrm, acc[v].y);
                acc[v].z = fmaf(hv.z, nrm, acc[v].z);
                acc[v].w = fmaf(hv.w, nrm, acc[v].w);
            }
        }
    }

    float4* od = reinterpret_cast<float4*>(out + (size_t)d * F);
    #pragma unroll
    for (int v = 0; v < V; v++) od[lane + 32 * v] = acc[v];
}

// ---------------- decode: out[e] = dot(z[src[e]], z[dst[e]]) over 128 ----------------
__global__ __launch_bounds__(256)
void k_decode(const float* __restrict__ z, const int* __restrict__ src,
              const int* __restrict__ dst, float* __restrict__ out, int E) {
    int e = (blockIdx.x * blockDim.x + threadIdx.x) >> 5;
    int lane = threadIdx.x & 31;
    if (e >= E) return;
    int s = __ldg(&src[e]);
    int d = __ldg(&dst[e]);
    const float4* zs = reinterpret_cast<const float4*>(z + (size_t)s * OUT_CH);
    const float4* zd = reinterpret_cast<const float4*>(z + (size_t)d * OUT_CH);
    float4 a = __ldg(&zs[lane]);
    float4 b = __ldg(&zd[lane]);
    float dot = a.x * b.x + a.y * b.y + a.z * b.z + a.w * b.w;
    #pragma unroll
    for (int o = 16; o > 0; o >>= 1) dot += __shfl_xor_sync(0xFFFFFFFFu, dot, o);
    if (lane == 0) out[e] = dot;
}

// ---------------- launch ----------------
extern "C" void kernel_launch(void* const* d_in, const int* in_sizes, int n_in,
                              void* d_out, int out_size) {
    const float* x  = (const float*)d_in[0];
    const unsigned int* eiw = (const unsigned int*)d_in[1];   // int32 OR int64 words
    const float* W1 = (const float*)d_in[2];
    const float* b1 = (const float*)d_in[3];
    const float* W2 = (const float*)d_in[4];
    const float* b2 = (const float*)d_in[5];
    float* out = (float*)d_out;

    const int n = in_sizes[0] / IN_CH;          // 50000
    const int E = in_sizes[1] / 2;              // 1600000 (element count same for i32/i64)

    int *src, *dst, *cnt, *cursor, *rs, *csr;
    float *dis, *h1, *a1, *h2, *a2;
    cudaGetSymbolAddress((void**)&src,    g_src);
    cudaGetSymbolAddress((void**)&dst,    g_dst);
    cudaGetSymbolAddress((void**)&cnt,    g_cnt);
    cudaGetSymbolAddress((void**)&cursor, g_cursor);
    cudaGetSymbolAddress((void**)&rs,     g_rowstart);
    cudaGetSymbolAddress((void**)&csr,    g_csr_src);
    cudaGetSymbolAddress((void**)&dis,    g_dis);
    cudaGetSymbolAddress((void**)&h1,     g_h1);
    cudaGetSymbolAddress((void**)&a1,     g_a1);
    cudaGetSymbolAddress((void**)&h2,     g_h2);
    cudaGetSymbolAddress((void**)&a2,     g_a2);

    // CSR build (shared by both layers)
    k_zero2<<<(n + 255) / 256, 256>>>(cnt, cursor, n);
    k_detect64<<<1, 32>>>(eiw);
    k_normalize_hist<<<(E + 255) / 256, 256>>>(eiw, E);
    k_scan_dis<<<1, 1024>>>(cnt, rs, dis, n);
    k_fill<<<(E + 255) / 256, 256>>>(src, dst, rs, cursor, csr, E);

    // layer 1: h1 = x @ W1 ; a1 = agg(h1) + self + b1
    {
        dim3 grd(HID / 128, (n + 127) / 128);
        k_sgemm<false><<<grd, 256>>>(x, W1, h1, n, HID, IN_CH);
        k_agg<HID><<<(n + 7) / 8, 256>>>(h1, rs, csr, dis, b1, a1, n);
    }

    // layer 2: h2 = relu(a1) @ W2 ; a2 = agg(h2) + self + b2
    {
        dim3 grd(OUT_CH / 128, (n + 127) / 128);
        k_sgemm<true><<<grd, 256>>>(a1, W2, h2, n, OUT_CH, HID);
        k_agg<OUT_CH><<<(n + 7) / 8, 256>>>(h2, rs, csr, dis, b2, a2, n);
    }

    // decode original edges
    k_decode<<<(E + 7) / 8, 256>>>(a2, src, dst, out, E);
}

// round 13
// speedup vs baseline: 1.5012x; 1.0960x over previous
#include <cuda_runtime.h>
#include <math.h>

#define N_NODES 50000
#define IN_CH   256
#define HID     256
#define OUT_CH  128
#define MAX_E   1600000
#define SCAN_BLOCKS 64          // >= ceil(N_NODES/1024) = 49

// ---------------- scratch (static device globals; no allocation) ----------------
__device__ int   g_is64;                                // edge_index stored as int64?
__device__ int   g_src[MAX_E];
__device__ int   g_dst[MAX_E];
__device__ int   g_cnt[N_NODES];                        // in-degree (no self-loop)
__device__ int   g_cursor[N_NODES];                     // CSR fill cursors
__device__ int   g_rowstart[N_NODES + 1];               // CSR row offsets
__device__ int   g_csr_src[MAX_E];                      // CSR: src ids grouped by dst
__device__ int   g_bsum[SCAN_BLOCKS];                   // per-block scan sums
__device__ float g_dis[N_NODES];                        // rsqrt(deg) incl self-loop
__device__ float g_h1[(size_t)N_NODES * HID];           // x @ W1
__device__ float g_a1[(size_t)N_NODES * HID];           // aggregated layer-1 (pre-relu)
__device__ float g_h2[(size_t)N_NODES * OUT_CH];        // relu(a1) @ W2
__device__ float g_a2[(size_t)N_NODES * OUT_CH];        // aggregated layer-2 (z)

// ---------------- packed f32x2 FMA (Blackwell; ptxas never auto-fuses) ----------------
#define PACK_F32X2(out, lo, hi) \
    asm("mov.b64 %0, {%1, %2};" : "=l"(out) : "f"(lo), "f"(hi))
#define UNPACK_F32X2(lo, hi, in) \
    asm("mov.b64 {%0, %1}, %2;" : "=f"(lo), "=f"(hi) : "l"(in))
#define FMA_F32X2(acc, a, b) \
    asm("fma.rn.f32x2 %0, %1, %2, %0;" : "+l"(acc) : "l"(a), "l"(b))

// ---------------- zero init (graph-safe; avoids cudaMemsetAsync) ----------------
__global__ void k_zero2(int* __restrict__ a, int* __restrict__ b, int n) {
    int i = blockIdx.x * blockDim.x + threadIdx.x;
    if (i < n) { a[i] = 0; b[i] = 0; }
}

// ---------------- edge-index dtype detect ----------------
// int64 storage: little-endian (lo, hi) pairs; values < 50000 => hi word == 0.
// int32 storage: odd words are uniform in [0, 50000); 64 consecutive zeros impossible.
__global__ void k_detect64(const unsigned int* __restrict__ w) {
    if (blockIdx.x == 0 && threadIdx.x == 0) {
        int is64 = 1;
        #pragma unroll 1
        for (int i = 0; i < 64; i++)
            if (w[2 * i + 1] != 0u) { is64 = 0; break; }
        g_is64 = is64;
    }
}

// normalize to int32 src/dst + fused degree histogram
__global__ void k_normalize_hist(const unsigned int* __restrict__ w, int E) {
    int e = blockIdx.x * blockDim.x + threadIdx.x;
    if (e >= E) return;
    int s, d;
    if (g_is64) {
        s = (int)w[2 * (size_t)e];
        d = (int)w[2 * (size_t)E + 2 * (size_t)e];
    } else {
        s = (int)w[e];
        d = (int)w[(size_t)E + e];
    }
    g_src[e] = s;
    g_dst[e] = d;
    atomicAdd(&g_cnt[d], 1);
}

// ---------------- parallel 3-phase exclusive scan + deg_inv_sqrt ----------------
// Phase 1: per-block exclusive scan of cnt (1024 elems/block) + block sums + dis.
__global__ void k_scan1(const int* __restrict__ cnt, int* __restrict__ rs,
                        float* __restrict__ dis, int* __restrict__ bsum, int n) {
    __shared__ int tmp[1024];
    int t = threadIdx.x;
    int i = blockIdx.x * 1024 + t;
    int v = (i < n) ? cnt[i] : 0;
    if (i < n) dis[i] = rsqrtf((float)(v + 1));         // +1 self-loop
    tmp[t] = v;
    __syncthreads();
    #pragma unroll
    for (int off = 1; off < 1024; off <<= 1) {
        int add = (t >= off) ? tmp[t - off] : 0;
        __syncthreads();
        tmp[t] += add;
        __syncthreads();
    }
    if (i < n) rs[i] = tmp[t] - v;                      // exclusive within block
    if (t == 1023) bsum[blockIdx.x] = tmp[1023];        // inclusive block total
}

// Phase 2: one small block scans the block sums (exclusive) and writes rs[n].
__global__ void k_scan2(int* __restrict__ bsum, int* __restrict__ rs, int nb, int n) {
    __shared__ int tmp[SCAN_BLOCKS];
    int t = threadIdx.x;                                // blockDim.x == SCAN_BLOCKS
    int v = (t < nb) ? bsum[t] : 0;
    tmp[t] = v;
    __syncthreads();
    #pragma unroll
    for (int off = 1; off < SCAN_BLOCKS; off <<= 1) {
        int add = (t >= off) ? tmp[t - off] : 0;
        __syncthreads();
        tmp[t] += add;
        __syncthreads();
    }
    if (t < nb) bsum[t] = tmp[t] - v;                   // exclusive block offset
    if (t == SCAN_BLOCKS - 1) rs[n] = tmp[SCAN_BLOCKS - 1];  // grand total
}

// Phase 3: add block offsets.
__global__ void k_scan3(int* __restrict__ rs, const int* __restrict__ bsum, int n) {
    int i = blockIdx.x * blockDim.x + threadIdx.x;
    if (i < n) rs[i] += bsum[i >> 10];
}

__global__ void k_fill(const int* __restrict__ src, const int* __restrict__ dst,
                       const int* __restrict__ rs, int* __restrict__ cursor,
                       int* __restrict__ csr_src, int E) {
    int e = blockIdx.x * blockDim.x + threadIdx.x;
    if (e >= E) return;
    int d = dst[e];
    int pos = rs[d] + atomicAdd(&cursor[d], 1);
    csr_src[pos] = src[e];
}

// ---------------- GEMM: C[M,N] = act(A[M,K]) @ B[K,N] ----------------
// BM=128, BN=128, BK=16, 256 threads, 8x8 per thread, packed f32x2 FMA.
// Thread (tx,ty): rows row0+ty*8..+7, cols col0+tx*4..+3 and col0+64+tx*4..+3.
template<bool RELU_A>
__global__ __launch_bounds__(256, 2)
void k_sgemm(const float* __restrict__ A, const float* __restrict__ B,
             float* __restrict__ C, int M, int N, int K) {
    __shared__ float As[128][17];   // [m][k], padded
    __shared__ float Bs[16][128];   // [k][n]

    const int tid = threadIdx.x;
    const int tx = tid & 15, ty = tid >> 4;
    const int row0 = blockIdx.y * 128;
    const int col0 = blockIdx.x * 128;

    unsigned long long acc2[8][4];
    #pragma unroll
    for (int i = 0; i < 8; i++)
        #pragma unroll
        for (int p = 0; p < 4; p++) acc2[i][p] = 0ull;

    for (int k0 = 0; k0 < K; k0 += 16) {
        // A tile 128x16 = 512 float4, 2 per thread
        #pragma unroll
        for (int l = 0; l < 2; l++) {
            int idx = l * 256 + tid;
            int r = idx >> 2, c4 = idx & 3;
            int gr = row0 + r;
            float4 v = make_float4(0.f, 0.f, 0.f, 0.f);
            if (gr < M) v = *reinterpret_cast<const float4*>(&A[(size_t)gr * K + k0 + c4 * 4]);
            if (RELU_A) {
                v.x = fmaxf(v.x, 0.f); v.y = fmaxf(v.y, 0.f);
                v.z = fmaxf(v.z, 0.f); v.w = fmaxf(v.w, 0.f);
            }
            As[r][c4 * 4 + 0] = v.x; As[r][c4 * 4 + 1] = v.y;
            As[r][c4 * 4 + 2] = v.z; As[r][c4 * 4 + 3] = v.w;
        }
        // B tile 16x128 = 512 float4, 2 per thread, coalesced
        #pragma unroll
        for (int l = 0; l < 2; l++) {
            int idx = l * 256 + tid;
            int r = idx >> 5, c4 = idx & 31;
            float4 v = *reinterpret_cast<const float4*>(&B[(size_t)(k0 + r) * N + col0 + c4 * 4]);
            *reinterpret_cast<float4*>(&Bs[r][c4 * 4]) = v;
        }
        __syncthreads();

        #pragma unroll
        for (int kk = 0; kk < 16; kk++) {
            // B: two conflict-free float4 reads (cols tx*4 and 64+tx*4)
            float4 b0 = *reinterpret_cast<const float4*>(&Bs[kk][tx * 4]);
            float4 b1 = *reinterpret_cast<const float4*>(&Bs[kk][64 + tx * 4]);
            unsigned long long bp[4];
            PACK_F32X2(bp[0], b0.x, b0.y);
            PACK_F32X2(bp[1], b0.z, b0.w);
            PACK_F32X2(bp[2], b1.x, b1.y);
            PACK_F32X2(bp[3], b1.z, b1.w);
            #pragma unroll
            for (int i = 0; i < 8; i++) {
                float av = As[ty * 8 + i][kk];
                unsigned long long ap;
                PACK_F32X2(ap, av, av);
                FMA_F32X2(acc2[i][0], ap, bp[0]);
                FMA_F32X2(acc2[i][1], ap, bp[1]);
                FMA_F32X2(acc2[i][2], ap, bp[2]);
                FMA_F32X2(acc2[i][3], ap, bp[3]);
            }
        }
        __syncthreads();
    }

    #pragma unroll
    for (int i = 0; i < 8; i++) {
        int gr = row0 + ty * 8 + i;
        if (gr >= M) break;
        float4 v0, v1;
        UNPACK_F32X2(v0.x, v0.y, acc2[i][0]);
        UNPACK_F32X2(v0.z, v0.w, acc2[i][1]);
        UNPACK_F32X2(v1.x, v1.y, acc2[i][2]);
        UNPACK_F32X2(v1.z, v1.w, acc2[i][3]);
        *reinterpret_cast<float4*>(&C[(size_t)gr * N + col0 + tx * 4])      = v0;
        *reinterpret_cast<float4*>(&C[(size_t)gr * N + col0 + 64 + tx * 4]) = v1;
    }
}

// ---------------- CSR aggregation: out[d] = sum_{s in N(d)} h[s]*dis[s]*dis[d]
//                                           + h[d]*dis[d]^2 + bias ----------------
// One warp per dst node; register accumulation, 2-wide neighbor unroll for MLP.
template<int F>
__global__ __launch_bounds__(256)
void k_agg(const float* __restrict__ h, const int* __restrict__ rs,
           const int* __restrict__ csr_src, const float* __restrict__ dis,
           const float* __restrict__ bias, float* __restrict__ out, int n) {
    constexpr int V = F / 128;                          // float4s per lane (2 or 1)
    int d = (blockIdx.x * blockDim.x + threadIdx.x) >> 5;
    int lane = threadIdx.x & 31;
    if (d >= n) return;

    float dd = __ldg(&dis[d]);
    float s2 = dd * dd;
    const float4* hd = reinterpret_cast<const float4*>(h + (size_t)d * F);
    const float4* bb = reinterpret_cast<const float4*>(bias);

    float4 acc[V];
    #pragma unroll
    for (int v = 0; v < V; v++) {
        float4 hv = __ldg(&hd[lane + 32 * v]);
        float4 b4 = __ldg(&bb[lane + 32 * v]);
        acc[v].x = fmaf(hv.x, s2, b4.x);
        acc[v].y = fmaf(hv.y, s2, b4.y);
        acc[v].z = fmaf(hv.z, s2, b4.z);
        acc[v].w = fmaf(hv.w, s2, b4.w);
    }

    int i0 = __ldg(&rs[d]), i1 = __ldg(&rs[d + 1]);
    for (int base = i0; base < i1; base += 32) {
        int idx = base + lane;
        int sv = 0; float sd = 0.f;
        if (idx < i1) {
            sv = __ldg(&csr_src[idx]);
            sd = __ldg(&dis[sv]);
        }
        int cnt = min(32, i1 - base);
        int j = 0;
        // 2-wide unroll: 2*V independent LDG.128 in flight per step
        for (; j + 2 <= cnt; j += 2) {
            int sA     = __shfl_sync(0xFFFFFFFFu, sv, j);
            float nA   = __shfl_sync(0xFFFFFFFFu, sd, j) * dd;
            int sB     = __shfl_sync(0xFFFFFFFFu, sv, j + 1);
            float nB   = __shfl_sync(0xFFFFFFFFu, sd, j + 1) * dd;
            const float4* hA = reinterpret_cast<const float4*>(h + (size_t)sA * F);
            const float4* hB = reinterpret_cast<const float4*>(h + (size_t)sB * F);
            float4 va[V], vb[V];
            #pragma unroll
            for (int v = 0; v < V; v++) va[v] = __ldg(&hA[lane + 32 * v]);
            #pragma unroll
            for (int v = 0; v < V; v++) vb[v] = __ldg(&hB[lane + 32 * v]);
            #pragma unroll
            for (int v = 0; v < V; v++) {
                acc[v].x = fmaf(va[v].x, nA, acc[v].x);
                acc[v].y = fmaf(va[v].y, nA, acc[v].y);
                acc[v].z = fmaf(va[v].z, nA, acc[v].z);
                acc[v].w = fmaf(va[v].w, nA, acc[v].w);
                acc[v].x = fmaf(vb[v].x, nB, acc[v].x);
                acc[v].y = fmaf(vb[v].y, nB, acc[v].y);
                acc[v].z = fmaf(vb[v].z, nB, acc[v].z);
                acc[v].w = fmaf(vb[v].w, nB, acc[v].w);
            }
        }
        for (; j < cnt; j++) {
            int s     = __shfl_sync(0xFFFFFFFFu, sv, j);
            float nrm = __shfl_sync(0xFFFFFFFFu, sd, j) * dd;
            const float4* hs = reinterpret_cast<const float4*>(h + (size_t)s * F);
            #pragma unroll
            for (int v = 0; v < V; v++) {
                float4 hv = __ldg(&hs[lane + 32 * v]);
                acc[v].x = fmaf(hv.x, nrm, acc[v].x);
                acc[v].y = fmaf(hv.y, nrm, acc[v].y);
                acc[v].z = fmaf(hv.z, nrm, acc[v].z);
                acc[v].w = fmaf(hv.w, nrm, acc[v].w);
            }
        }
    }

    float4* od = reinterpret_cast<float4*>(out + (size_t)d * F);
    #pragma unroll
    for (int v = 0; v < V; v++) od[lane + 32 * v] = acc[v];
}

// ---------------- decode: out[e] = dot(z[src[e]], z[dst[e]]) over 128 ----------------
__global__ __launch_bounds__(256)
void k_decode(const float* __restrict__ z, const int* __restrict__ src,
              const int* __restrict__ dst, float* __restrict__ out, int E) {
    int e = (blockIdx.x * blockDim.x + threadIdx.x) >> 5;
    int lane = threadIdx.x & 31;
    if (e >= E) return;
    int s = __ldg(&src[e]);
    int d = __ldg(&dst[e]);
    const float4* zs = reinterpret_cast<const float4*>(z + (size_t)s * OUT_CH);
    const float4* zd = reinterpret_cast<const float4*>(z + (size_t)d * OUT_CH);
    float4 a = __ldg(&zs[lane]);
    float4 b = __ldg(&zd[lane]);
    float dot = a.x * b.x + a.y * b.y + a.z * b.z + a.w * b.w;
    #pragma unroll
    for (int o = 16; o > 0; o >>= 1) dot += __shfl_xor_sync(0xFFFFFFFFu, dot, o);
    if (lane == 0) out[e] = dot;
}

// ---------------- launch ----------------
extern "C" void kernel_launch(void* const* d_in, const int* in_sizes, int n_in,
                              void* d_out, int out_size) {
    const float* x  = (const float*)d_in[0];
    const unsigned int* eiw = (const unsigned int*)d_in[1];   // int32 OR int64 words
    const float* W1 = (const float*)d_in[2];
    const float* b1 = (const float*)d_in[3];
    const float* W2 = (const float*)d_in[4];
    const float* b2 = (const float*)d_in[5];
    float* out = (float*)d_out;

    const int n = in_sizes[0] / IN_CH;          // 50000
    const int E = in_sizes[1] / 2;              // 1600000 (element count same for i32/i64)

    int *src, *dst, *cnt, *cursor, *rs, *csr, *bsum;
    float *dis, *h1, *a1, *h2, *a2;
    cudaGetSymbolAddress((void**)&src,    g_src);
    cudaGetSymbolAddress((void**)&dst,    g_dst);
    cudaGetSymbolAddress((void**)&cnt,    g_cnt);
    cudaGetSymbolAddress((void**)&cursor, g_cursor);
    cudaGetSymbolAddress((void**)&rs,     g_rowstart);
    cudaGetSymbolAddress((void**)&csr,    g_csr_src);
    cudaGetSymbolAddress((void**)&bsum,   g_bsum);
    cudaGetSymbolAddress((void**)&dis,    g_dis);
    cudaGetSymbolAddress((void**)&h1,     g_h1);
    cudaGetSymbolAddress((void**)&a1,     g_a1);
    cudaGetSymbolAddress((void**)&h2,     g_h2);
    cudaGetSymbolAddress((void**)&a2,     g_a2);

    const int nscan = (n + 1023) / 1024;        // 49 <= SCAN_BLOCKS

    // CSR build (shared by both layers)
    k_zero2<<<(n + 255) / 256, 256>>>(cnt, cursor, n);
    k_detect64<<<1, 32>>>(eiw);
    k_normalize_hist<<<(E + 255) / 256, 256>>>(eiw, E);
    k_scan1<<<nscan, 1024>>>(cnt, rs, dis, bsum, n);
    k_scan2<<<1, SCAN_BLOCKS>>>(bsum, rs, nscan, n);
    k_scan3<<<(n + 255) / 256, 256>>>(rs, bsum, n);
    k_fill<<<(E + 255) / 256, 256>>>(src, dst, rs, cursor, csr, E);

    // layer 1: h1 = x @ W1 ; a1 = agg(h1) + self + b1
    {
        dim3 grd(HID / 128, (n + 127) / 128);
        k_sgemm<false><<<grd, 256>>>(x, W1, h1, n, HID, IN_CH);
        k_agg<HID><<<(n + 7) / 8, 256>>>(h1, rs, csr, dis, b1, a1, n);
    }

    // layer 2: h2 = relu(a1) @ W2 ; a2 = agg(h2) + self + b2
    {
        dim3 grd(OUT_CH / 128, (n + 127) / 128);
        k_sgemm<true><<<grd, 256>>>(a1, W2, h2, n, OUT_CH, HID);
        k_agg<OUT_CH><<<(n + 7) / 8, 256>>>(h2, rs, csr, dis, b2, a2, n);
    }

    // decode original edges
    k_decode<<<(E + 7) / 8, 256>>>(a2, src, dst, out, E);
}